// round 12
// baseline (speedup 1.0000x reference)
#include <cuda_runtime.h>
#include <cuda_bf16.h>
#include <math.h>
#include <stdint.h>

// GCN1: 3-layer GCN over 4 graphs, shared weights, scalar-mean output.
// R12: all inter-stage features bf16 (gather bytes halved -- now that loads
//      are vectorized the SpMM is byte-bound, R11 proved the instr floor is
//      gone), shift-based bf16 unpack, layer-1 SpMM half-warp edge split.

#define NN 50000
#define EE 800000
#define FH 304
#define FI 128
#define NG 4
#define NB 196   // ceil(NN/256)

// ---------------- scratch (__device__ only; never passed as kernel args) ----
__device__ __align__(128) uint32_t g_bufAh[(size_t)NN * 160]; // SpMM out bf16x2 (padded)
__device__ __align__(128) uint32_t g_bufBh[(size_t)NN * 152]; // GEMM out bf16x2
__device__ __align__(128) uint32_t g_xbf[NG][(size_t)NN * 64];// x as bf16x2
__device__ __align__(128) uint32_t g_Wh1[320 * 64];           // [Npad][K/2] bf16x2
__device__ __align__(128) uint32_t g_Wh2[320 * 160];
__device__ __align__(128) uint32_t g_Wh3[320 * 160];
__device__ float g_ns[NG][NN];
__device__ float g_nd[NG][NN];
__device__ int   g_deg_s[NG][NN];
__device__ int   g_deg_d[NG][NN];
__device__ int   g_rowoff[NG][NN + 1];
__device__ int   g_cursor[NG][NN];
__device__ int   g_csr[NG][EE];
__device__ int   g_bsum[NG][256];
__device__ int   g_boff[NG][256];
__device__ double g_sum;

// ---------------- helpers ----------------------------------------------------
__device__ __forceinline__ uint32_t packbf(float x, float y) {
    __nv_bfloat162 b = __float22bfloat162_rn(make_float2(x, y));
    return *(uint32_t*)&b;
}
// fma 8 bf16 values (one uint4) into acc[8]; bf16->fp32 is a shift (ALU pipe)
__device__ __forceinline__ void bfma8(float* acc, uint4 u, float w) {
    acc[0] += w * __uint_as_float(u.x << 16);
    acc[1] += w * __uint_as_float(u.x & 0xffff0000u);
    acc[2] += w * __uint_as_float(u.y << 16);
    acc[3] += w * __uint_as_float(u.y & 0xffff0000u);
    acc[4] += w * __uint_as_float(u.z << 16);
    acc[5] += w * __uint_as_float(u.z & 0xffff0000u);
    acc[6] += w * __uint_as_float(u.w << 16);
    acc[7] += w * __uint_as_float(u.w & 0xffff0000u);
}
__device__ __forceinline__ uint4 pack8(const float* a, float nd) {
    uint4 o;
    o.x = packbf(a[0] * nd, a[1] * nd);
    o.y = packbf(a[2] * nd, a[3] * nd);
    o.z = packbf(a[4] * nd, a[5] * nd);
    o.w = packbf(a[6] * nd, a[7] * nd);
    return o;
}

// ---------------- small kernels ---------------------------------------------
__global__ void k_init() { g_sum = 0.0; }

// W[K][FH] -> Wh[Npad=320][Kp/2] packed bf16x2, zero-padded
__global__ void k_prep_wh(const float* __restrict__ W, int sel, int K, int Kp2) {
    int id = blockIdx.x * blockDim.x + threadIdx.x;
    if (id >= 320 * Kp2) return;
    int n = id / Kp2, kw = id % Kp2;
    int k = 2 * kw;
    float v0 = (k < K && n < FH) ? W[(size_t)k * FH + n] : 0.f;
    float v1 = (k + 1 < K && n < FH) ? W[(size_t)(k + 1) * FH + n] : 0.f;
    uint32_t* dst = (sel == 0) ? g_Wh1 : (sel == 1) ? g_Wh2 : g_Wh3;
    dst[(size_t)n * Kp2 + kw] = packbf(v0, v1);
}

// convert all 4 graphs' x to bf16x2, batched
__global__ void k_xconv(const float* __restrict__ x0, const float* __restrict__ x1,
                        const float* __restrict__ x2, const float* __restrict__ x3) {
    int g = blockIdx.y;
    const float* x = (g == 0) ? x0 : (g == 1) ? x1 : (g == 2) ? x2 : x3;
    int i = blockIdx.x * blockDim.x + threadIdx.x;   // pair index
    if (i < NN * 64) {
        float2 f = *(const float2*)(x + 2 * (size_t)i);
        g_xbf[g][i] = packbf(f.x, f.y);
    }
}

__global__ void k_zero() {
    int g = blockIdx.y;
    int i = blockIdx.x * blockDim.x + threadIdx.x;
    if (i < NN) { g_deg_s[g][i] = 0; g_deg_d[g][i] = 0; }
}

__global__ void k_deg(const int* __restrict__ s0, const int* __restrict__ d0,
                      const int* __restrict__ s1, const int* __restrict__ d1,
                      const int* __restrict__ s2, const int* __restrict__ d2,
                      const int* __restrict__ s3, const int* __restrict__ d3) {
    int g = blockIdx.y;
    const int* s = (g == 0) ? s0 : (g == 1) ? s1 : (g == 2) ? s2 : s3;
    const int* d = (g == 0) ? d0 : (g == 1) ? d1 : (g == 2) ? d2 : d3;
    int e = blockIdx.x * blockDim.x + threadIdx.x;
    if (e < EE) {
        atomicAdd(&g_deg_s[g][s[e]], 1);
        atomicAdd(&g_deg_d[g][d[e]], 1);
    }
}

__global__ void k_scan1() {
    int g = blockIdx.y, t = threadIdx.x;
    int i = blockIdx.x * 256 + t;
    __shared__ int sm[256];
    sm[t] = (i < NN) ? g_deg_d[g][i] : 0;
    __syncthreads();
    for (int o = 128; o > 0; o >>= 1) {
        if (t < o) sm[t] += sm[t + o];
        __syncthreads();
    }
    if (t == 0) g_bsum[g][blockIdx.x] = sm[0];
}

__global__ void k_scan2() {
    int g = blockIdx.y, t = threadIdx.x;
    int v = (t < NB) ? g_bsum[g][t] : 0;
    __shared__ int sm[256];
    sm[t] = v;
    __syncthreads();
    for (int o = 1; o < 256; o <<= 1) {
        int a = (t >= o) ? sm[t - o] : 0;
        __syncthreads();
        sm[t] += a;
        __syncthreads();
    }
    g_boff[g][t] = sm[t] - v;  // exclusive
}

__global__ void k_scan3() {
    int g = blockIdx.y, t = threadIdx.x;
    int i = blockIdx.x * 256 + t;
    int d = (i < NN) ? g_deg_d[g][i] : 0;
    __shared__ int sm[256];
    sm[t] = d;
    __syncthreads();
    for (int o = 1; o < 256; o <<= 1) {
        int a = (t >= o) ? sm[t - o] : 0;
        __syncthreads();
        sm[t] += a;
        __syncthreads();
    }
    int off = g_boff[g][blockIdx.x] + sm[t] - d;  // exclusive
    if (i < NN) {
        g_rowoff[g][i] = off;
        g_cursor[g][i] = off;
        g_nd[g][i] = rsqrtf((float)max(d, 1));
        g_ns[g][i] = rsqrtf((float)max(g_deg_s[g][i], 1));
    }
    if (blockIdx.x == 0 && t == 0) g_rowoff[g][NN] = EE;
}

__global__ void k_scatter(const int* __restrict__ s0, const int* __restrict__ d0,
                          const int* __restrict__ s1, const int* __restrict__ d1,
                          const int* __restrict__ s2, const int* __restrict__ d2,
                          const int* __restrict__ s3, const int* __restrict__ d3) {
    int g = blockIdx.y;
    const int* s = (g == 0) ? s0 : (g == 1) ? s1 : (g == 2) ? s2 : s3;
    const int* d = (g == 0) ? d0 : (g == 1) ? d1 : (g == 2) ? d2 : d3;
    int e = blockIdx.x * blockDim.x + threadIdx.x;
    if (e < EE) {
        int p = atomicAdd(&g_cursor[g][d[e]], 1);
        g_csr[g][p] = s[e];
    }
}

// Layer-1 SpMM: warp-per-dst over bf16 x rows (64 words = 16 uint4).
// Half-warp split: lanes 0-15 even edges, 16-31 odd edges; shfl_xor(16) merge.
__global__ void __launch_bounds__(256)
k_spmm1(int g) {
    int n = blockIdx.x * 8 + (threadIdx.x >> 5);
    if (n >= NN) return;
    int lane = threadIdx.x & 31;
    int half = lane >> 4, slot = lane & 15;
    int beg = g_rowoff[g][n], end = g_rowoff[g][n + 1];
    const uint32_t* __restrict__ hb = g_xbf[g];
    float acc[8];
#pragma unroll
    for (int i = 0; i < 8; i++) acc[i] = 0.f;
    for (int j = beg; j < end; j += 2) {
        int sA = g_csr[g][j];
        int okB = (j + 1 < end);
        int sB = okB ? g_csr[g][j + 1] : sA;
        int s = half ? sB : sA;
        float w = half ? (okB ? g_ns[g][sB] : 0.f) : g_ns[g][sA];
        uint4 u = *(const uint4*)(hb + (size_t)s * 64 + 4 * slot);
        bfma8(acc, u, w);
    }
#pragma unroll
    for (int i = 0; i < 8; i++)
        acc[i] += __shfl_xor_sync(0xffffffffu, acc[i], 16);
    if (half == 0) {
        float nd = g_nd[g][n];
        *(uint4*)(g_bufAh + (size_t)n * 64 + 4 * slot) = pack8(acc, nd);
    }
}

// Layers 2/3 SpMM: warp-per-dst over bf16 rows (152 words = 38 uint4).
// Lane reads slot lane; lanes 0-5 also slot 32+lane. Output padded to 160.
__global__ void __launch_bounds__(256)
k_spmm23(int g) {
    int n = blockIdx.x * 8 + (threadIdx.x >> 5);
    if (n >= NN) return;
    int lane = threadIdx.x & 31;
    int beg = g_rowoff[g][n], end = g_rowoff[g][n + 1];
    float acc[8], accx[8];
#pragma unroll
    for (int i = 0; i < 8; i++) { acc[i] = 0.f; accx[i] = 0.f; }
    int j = beg;
    for (; j + 1 < end; j += 2) {
        int sA = g_csr[g][j], sB = g_csr[g][j + 1];
        float wA = g_ns[g][sA], wB = g_ns[g][sB];
        const uint32_t* rA = g_bufBh + (size_t)sA * 152;
        const uint32_t* rB = g_bufBh + (size_t)sB * 152;
        uint4 uA = *(const uint4*)(rA + 4 * lane);
        uint4 uB = *(const uint4*)(rB + 4 * lane);
        bfma8(acc, uA, wA);
        bfma8(acc, uB, wB);
        if (lane < 6) {
            uint4 vA = *(const uint4*)(rA + 128 + 4 * lane);
            uint4 vB = *(const uint4*)(rB + 128 + 4 * lane);
            bfma8(accx, vA, wA);
            bfma8(accx, vB, wB);
        }
    }
    if (j < end) {
        int s = g_csr[g][j];
        float w = g_ns[g][s];
        const uint32_t* r = g_bufBh + (size_t)s * 152;
        uint4 u = *(const uint4*)(r + 4 * lane);
        bfma8(acc, u, w);
        if (lane < 6) {
            uint4 v = *(const uint4*)(r + 128 + 4 * lane);
            bfma8(accx, v, w);
        }
    }
    float nd = g_nd[g][n];
    uint32_t* o = g_bufAh + (size_t)n * 160;
    *(uint4*)(o + 4 * lane) = pack8(acc, nd);
    if (lane < 6)
        *(uint4*)(o + 128 + 4 * lane) = pack8(accx, nd);
    else if (lane < 8)
        *(uint4*)(o + 128 + 4 * lane) = make_uint4(0u, 0u, 0u, 0u);  // pad 152..159
}

// ---------------- bf16 mma.sync GEMM ----------------------------------------
// relu(bf16 A @ Wh^T + bias) -> g_bufBh (bf16x2), or (dosum) scalar sum only.
__device__ __forceinline__ void mma16(float* d, const uint32_t* a, const uint32_t* b) {
    asm volatile("mma.sync.aligned.m16n8k16.row.col.f32.bf16.bf16.f32 "
                 "{%0,%1,%2,%3}, {%4,%5,%6,%7}, {%8,%9}, {%0,%1,%2,%3};"
                 : "+f"(d[0]), "+f"(d[1]), "+f"(d[2]), "+f"(d[3])
                 : "r"(a[0]), "r"(a[1]), "r"(a[2]), "r"(a[3]),
                   "r"(b[0]), "r"(b[1]));
}

#define PADW 20  // 16 words + 4 pad

__global__ void __launch_bounds__(256)
k_gemm_mma(const float* __restrict__ bias, int wsel, int NC, int wstride, int dosum) {
    __shared__ uint32_t As[128][PADW];   // bf16x2 words along k
    __shared__ uint32_t Bs[64][PADW];
    __shared__ float wsum[8];

    const uint32_t* __restrict__ Wh = (wsel == 0) ? g_Wh1 : (wsel == 1) ? g_Wh2 : g_Wh3;
    const int Kp2 = NC * 16;

    int tid = threadIdx.x, wid = tid >> 5, lane = tid & 31;
    int wm = wid & 3, wn = wid >> 2;
    int rowBase = blockIdx.x * 128;
    int colBase = blockIdx.y * 64;

    float acc[2][4][4];
#pragma unroll
    for (int mi = 0; mi < 2; mi++)
#pragma unroll
        for (int ni = 0; ni < 4; ni++)
#pragma unroll
            for (int q = 0; q < 4; q++) acc[mi][ni][q] = 0.f;

    int ar = tid >> 2, aw = tid & 3;
    int br = tid >> 2, bw = tid & 3;
    uint4 aU[2], bU;

    {   // prefetch chunk 0
#pragma unroll
        for (int j = 0; j < 2; j++) {
            int gr = rowBase + ar + j * 64;
            aU[j] = (gr < NN)
                ? *(const uint4*)(g_bufAh + (size_t)gr * wstride + aw * 4)
                : make_uint4(0u, 0u, 0u, 0u);
        }
        bU = *(const uint4*)(Wh + (size_t)(colBase + br) * Kp2 + bw * 4);
    }

    for (int c = 0; c < NC; c++) {
#pragma unroll
        for (int j = 0; j < 2; j++)
            *(uint4*)&As[ar + j * 64][aw * 4] = aU[j];
        *(uint4*)&Bs[br][bw * 4] = bU;
        __syncthreads();

        if (c + 1 < NC) {
            int kw0 = (c + 1) * 16;
#pragma unroll
            for (int j = 0; j < 2; j++) {
                int gr = rowBase + ar + j * 64;
                aU[j] = (gr < NN)
                    ? *(const uint4*)(g_bufAh + (size_t)gr * wstride + kw0 + aw * 4)
                    : make_uint4(0u, 0u, 0u, 0u);
            }
            bU = *(const uint4*)(Wh + (size_t)(colBase + br) * Kp2 + kw0 + bw * 4);
        }

        int g = lane >> 2, cc = lane & 3;
#pragma unroll
        for (int kw = 0; kw < 16; kw += 8) {
            uint32_t af[2][4], bf[4][2];
#pragma unroll
            for (int mi = 0; mi < 2; mi++) {
                int base = wm * 32 + mi * 16 + g;
                af[mi][0] = As[base][kw + cc];
                af[mi][1] = As[base + 8][kw + cc];
                af[mi][2] = As[base][kw + cc + 4];
                af[mi][3] = As[base + 8][kw + cc + 4];
            }
#pragma unroll
            for (int ni = 0; ni < 4; ni++) {
                int nb = wn * 32 + ni * 8 + g;
                bf[ni][0] = Bs[nb][kw + cc];
                bf[ni][1] = Bs[nb][kw + cc + 4];
            }
#pragma unroll
            for (int mi = 0; mi < 2; mi++)
#pragma unroll
                for (int ni = 0; ni < 4; ni++)
                    mma16(acc[mi][ni], af[mi], bf[ni]);
        }
        __syncthreads();
    }

    // epilogue: bias + relu; store bf16x2 (layers 1-2) or scalar sum (layer 3)
    float lsum = 0.f;
    int g = lane >> 2, cc = lane & 3;
#pragma unroll
    for (int mi = 0; mi < 2; mi++) {
        int r0 = rowBase + wm * 32 + mi * 16 + g;
#pragma unroll
        for (int ni = 0; ni < 4; ni++) {
            int c0 = colBase + wn * 32 + ni * 8 + cc * 2;
            if (c0 < FH) {
                float bz0 = bias[c0], bz1 = bias[c0 + 1];
                float v0 = fmaxf(acc[mi][ni][0] + bz0, 0.f);
                float v1 = fmaxf(acc[mi][ni][1] + bz1, 0.f);
                float v2 = fmaxf(acc[mi][ni][2] + bz0, 0.f);
                float v3 = fmaxf(acc[mi][ni][3] + bz1, 0.f);
                if (dosum) {
                    if (r0 < NN)     lsum += v0 + v1;
                    if (r0 + 8 < NN) lsum += v2 + v3;
                } else {
                    if (r0 < NN)
                        g_bufBh[(size_t)r0 * 152 + (c0 >> 1)] = packbf(v0, v1);
                    if (r0 + 8 < NN)
                        g_bufBh[(size_t)(r0 + 8) * 152 + (c0 >> 1)] = packbf(v2, v3);
                }
            }
        }
    }
    if (dosum) {
#pragma unroll
        for (int o = 16; o > 0; o >>= 1) lsum += __shfl_down_sync(0xffffffffu, lsum, o);
        if (lane == 0) wsum[wid] = lsum;
        __syncthreads();
        if (tid == 0) {
            double tot = 0.0;
#pragma unroll
            for (int w = 0; w < 8; w++) tot += (double)wsum[w];
            atomicAdd(&g_sum, tot);
        }
    }
}

__global__ void k_final(float* __restrict__ out) {
    out[0] = (float)(g_sum / (4.0 * NN * FH));
}

// ---------------- launch -----------------------------------------------------
extern "C" void kernel_launch(void* const* d_in, const int* in_sizes, int n_in,
                              void* d_out, int out_size) {
    const float* X[4];   int nx = 0;
    const int*   EDG[8]; int ne = 0;
    const float* W[3] = {0, 0, 0};
    const float* Bv[3]; int nb = 0;
    int nw2 = 0;
    for (int i = 0; i < n_in; i++) {
        int sz = in_sizes[i];
        if (sz == 6400000)      X[nx++]   = (const float*)d_in[i];
        else if (sz == 800000)  EDG[ne++] = (const int*)d_in[i];
        else if (sz == 38912)   W[0] = (const float*)d_in[i];
        else if (sz == 92416)   { W[1 + nw2] = (const float*)d_in[i]; nw2++; }
        else if (sz == 304)     Bv[nb++] = (const float*)d_in[i];
    }
    float* out = (float*)d_out;

    k_init<<<1, 1>>>();
    k_prep_wh<<<(320 * 64 + 255) / 256, 256>>>(W[0], 0, 128, 64);
    k_prep_wh<<<(320 * 160 + 255) / 256, 256>>>(W[1], 1, 304, 160);
    k_prep_wh<<<(320 * 160 + 255) / 256, 256>>>(W[2], 2, 304, 160);
    k_xconv<<<dim3((NN * 64 + 255) / 256, NG), 256>>>(X[0], X[1], X[2], X[3]);

    // batched CSR build for all 4 graphs
    k_zero<<<dim3(NB, NG), 256>>>();
    k_deg<<<dim3(EE / 256, NG), 256>>>(EDG[0], EDG[1], EDG[2], EDG[3],
                                       EDG[4], EDG[5], EDG[6], EDG[7]);
    k_scan1<<<dim3(NB, NG), 256>>>();
    k_scan2<<<dim3(1, NG), 256>>>();
    k_scan3<<<dim3(NB, NG), 256>>>();
    k_scatter<<<dim3(EE / 256, NG), 256>>>(EDG[0], EDG[1], EDG[2], EDG[3],
                                           EDG[4], EDG[5], EDG[6], EDG[7]);

    dim3 gemmGrid((NN + 127) / 128, 5);  // N padded to 320
    const int spmmGrid = NN / 8;         // 6250 blocks x 8 warps
    for (int g = 0; g < 4; g++) {
        k_spmm1<<<spmmGrid, 256>>>(g);
        k_gemm_mma<<<gemmGrid, 256>>>(Bv[0], 0, 4, 64, 0);
        k_spmm23<<<spmmGrid, 256>>>(g);
        k_gemm_mma<<<gemmGrid, 256>>>(Bv[1], 1, 10, 160, 0);
        k_spmm23<<<spmmGrid, 256>>>(g);
        k_gemm_mma<<<gemmGrid, 256>>>(Bv[2], 2, 10, 160, 1);
    }
    k_final<<<1, 1>>>(out);
}